// round 14
// baseline (speedup 1.0000x reference)
#include <cuda_runtime.h>
#include <cuda_fp16.h>
#include <mma.h>
#include <math.h>

using namespace nvcuda;

#define NNODES 50000
#define NEDGES 400000
#define FDIM   128
#define F3     384
#define NB     20
#define EPB    128
#define SCAN_NBLK 49   // ceil(50000/1024)

__device__ __half g_h [(size_t)NNODES * FDIM];
__device__ __half g_so[(size_t)NNODES * F3];
__device__ __half g_nvh[(size_t)NNODES * F3];
__device__ __half g_W1h[FDIM * FDIM];
__device__ __half g_W2h[FDIM * F3];

// counting-sort scratch
__device__ unsigned g_cnt[NNODES];
__device__ unsigned g_cur[NNODES];
__device__ unsigned g_start[NNODES];
__device__ unsigned g_bsum[64];
__device__ int2     g_sids[NEDGES];     // (dst, src) sorted by dst
__device__ float4   g_sgeo[NEDGES];     // (diffx, diffy, diffz, dist)

// ---------------------------------------------------------------------------
// out = concat(node_scalar, node_vector); emit nv as fp16 (nsh no longer needed)
// ---------------------------------------------------------------------------
__global__ void copy_init_kernel(const float4* __restrict__ ns,
                                 const float4* __restrict__ nv,
                                 float4* __restrict__ out,
                                 uint2* __restrict__ nvh) {
    const int NS4 = NNODES * FDIM / 4;
    const int NT4 = NS4 + NNODES * F3 / 4;
    int i = blockIdx.x * blockDim.x + threadIdx.x;
    if (i >= NT4) return;
    if (i < NS4) {
        out[i] = ns[i];
    } else {
        float4 v = nv[i - NS4];
        out[i] = v;
        __half2 h0 = __floats2half2_rn(v.x, v.y);
        __half2 h1 = __floats2half2_rn(v.z, v.w);
        nvh[i - NS4] = make_uint2(*(unsigned*)&h0, *(unsigned*)&h1);
    }
}

// convert BOTH weight matrices in one launch
__global__ void f2h_weights_kernel(const float4* __restrict__ w1,
                                   const float4* __restrict__ w2,
                                   uint2* __restrict__ w1h,
                                   uint2* __restrict__ w2h) {
    const int N1 = FDIM * FDIM / 4;
    const int NT = N1 + FDIM * F3 / 4;
    int i = blockIdx.x * blockDim.x + threadIdx.x;
    if (i >= NT) return;
    float4 v;
    if (i < N1) v = w1[i]; else v = w2[i - N1];
    __half2 h0 = __floats2half2_rn(v.x, v.y);
    __half2 h1 = __floats2half2_rn(v.z, v.w);
    uint2 o = make_uint2(*(unsigned*)&h0, *(unsigned*)&h1);
    if (i < N1) w1h[i] = o; else w2h[i - N1] = o;
}

__device__ __forceinline__ float4 ld_half4(const __half* p) {
    uint2 u = *(const uint2*)p;
    __half2 h0 = *reinterpret_cast<__half2*>(&u.x);
    __half2 h1 = *reinterpret_cast<__half2*>(&u.y);
    float2 f0 = __half22float2(h0), f1 = __half22float2(h1);
    return make_float4(f0.x, f0.y, f1.x, f1.y);
}

// ---------------------------------------------------------------------------
// counting sort by dst — hierarchical scan
// ---------------------------------------------------------------------------
__global__ void zero_kernel(unsigned* a, unsigned* b) {
    int i = blockIdx.x * blockDim.x + threadIdx.x;
    if (i < NNODES) { a[i] = 0u; b[i] = 0u; }
}

__global__ void hist_kernel(const int2* __restrict__ eidx, unsigned* cnt) {
    int e = blockIdx.x * blockDim.x + threadIdx.x;
    if (e < NEDGES) atomicAdd(&cnt[eidx[e].x], 1u);
}

__global__ void blocksum_kernel(const unsigned* __restrict__ cnt,
                                unsigned* __restrict__ bsum) {
    __shared__ unsigned sh[256];
    int base = blockIdx.x * 1024;
    unsigned s = 0;
#pragma unroll
    for (int j = 0; j < 4; j++) {
        int idx = base + threadIdx.x + j * 256;
        if (idx < NNODES) s += cnt[idx];
    }
    sh[threadIdx.x] = s;
    __syncthreads();
    for (int off = 128; off > 0; off >>= 1) {
        if (threadIdx.x < off) sh[threadIdx.x] += sh[threadIdx.x + off];
        __syncthreads();
    }
    if (threadIdx.x == 0) bsum[blockIdx.x] = sh[0];
}

__global__ void bsum_scan_kernel(unsigned* bsum) {
    __shared__ unsigned sh[64];
    unsigned v = (threadIdx.x < SCAN_NBLK) ? bsum[threadIdx.x] : 0u;
    sh[threadIdx.x] = v;
    __syncthreads();
    for (int off = 1; off < 64; off <<= 1) {
        unsigned t = (threadIdx.x >= (unsigned)off) ? sh[threadIdx.x - off] : 0u;
        __syncthreads();
        sh[threadIdx.x] += t;
        __syncthreads();
    }
    if (threadIdx.x < SCAN_NBLK) bsum[threadIdx.x] = sh[threadIdx.x] - v;
}

__global__ void block_scan_kernel(const unsigned* __restrict__ cnt,
                                  const unsigned* __restrict__ bsum,
                                  unsigned* __restrict__ start) {
    __shared__ unsigned sh[256];
    int base = blockIdx.x * 1024;
    unsigned v[4];
    unsigned s = 0;
#pragma unroll
    for (int j = 0; j < 4; j++) {
        int idx = base + (int)threadIdx.x * 4 + j;
        v[j] = (idx < NNODES) ? cnt[idx] : 0u;
        s += v[j];
    }
    sh[threadIdx.x] = s;
    __syncthreads();
    for (int off = 1; off < 256; off <<= 1) {
        unsigned t = (threadIdx.x >= (unsigned)off) ? sh[threadIdx.x - off] : 0u;
        __syncthreads();
        sh[threadIdx.x] += t;
        __syncthreads();
    }
    unsigned ex = bsum[blockIdx.x] + sh[threadIdx.x] - s;
#pragma unroll
    for (int j = 0; j < 4; j++) {
        int idx = base + (int)threadIdx.x * 4 + j;
        if (idx < NNODES) start[idx] = ex;
        ex += v[j];
    }
}

__global__ void scatter_kernel(const int2*  __restrict__ eidx,
                               const float* __restrict__ edist,
                               const float* __restrict__ ediff,
                               const unsigned* __restrict__ start,
                               unsigned* __restrict__ cur,
                               int2* __restrict__ sids,
                               float4* __restrict__ sgeo) {
    int e = blockIdx.x * blockDim.x + threadIdx.x;
    if (e >= NEDGES) return;
    int2 ei = eidx[e];
    unsigned pos = start[ei.x] + atomicAdd(&cur[ei.x], 1u);
    sids[pos] = ei;
    sgeo[pos] = make_float4(ediff[3*e], ediff[3*e+1], ediff[3*e+2], edist[e]);
}

// ---------------------------------------------------------------------------
// Tensor-core node MLP GEMM. AF32: A operand read as fp32, converted in the
// smem-load path (removes the nsh dependency on copy_init).
// ---------------------------------------------------------------------------
template<bool SILU, bool AF32>
__global__ __launch_bounds__(256)
void hgemm_kernel(const void* __restrict__ Av, const __half* __restrict__ W,
                  const float* __restrict__ bias, __half* __restrict__ C,
                  int M, int N)
{
    const int K = 128, BM = 128, BK = 32;
    const int LDA = 48, LDB = 72, LDE = 36;
    __shared__ __half As[BM * LDA];
    __shared__ __half Bs[BK * LDB];
    __shared__ float  Es[8][16 * LDE];

    int t = threadIdx.x;
    int warp = t >> 5, lane = t & 31;
    int wm = warp >> 1, wn = warp & 1;
    int m0 = blockIdx.x * BM;
    int n0 = blockIdx.y * 64;

    wmma::fragment<wmma::accumulator, 16, 16, 16, float> acc[2][2];
#pragma unroll
    for (int i = 0; i < 2; i++)
#pragma unroll
        for (int j = 0; j < 2; j++) wmma::fill_fragment(acc[i][j], 0.0f);

    int arow = t >> 1, acolh = (t & 1) << 4;
    int brow = t >> 3, bcolh = (t & 7) << 3;

#pragma unroll 1
    for (int k0 = 0; k0 < K; k0 += BK) {
        if (AF32) {
            const float* A = (const float*)Av;
            __half hv[16];
#pragma unroll
            for (int q = 0; q < 16; q++) hv[q] = __float2half_rn(0.f);
            if (m0 + arow < M) {
                const float* ap = A + (size_t)(m0 + arow) * K + k0 + acolh;
#pragma unroll
                for (int q = 0; q < 4; q++) {
                    float4 f = *(const float4*)(ap + q * 4);
                    hv[q*4+0] = __float2half_rn(f.x);
                    hv[q*4+1] = __float2half_rn(f.y);
                    hv[q*4+2] = __float2half_rn(f.z);
                    hv[q*4+3] = __float2half_rn(f.w);
                }
            }
            *(uint4*)(As + arow * LDA + acolh)     = ((uint4*)hv)[0];
            *(uint4*)(As + arow * LDA + acolh + 8) = ((uint4*)hv)[1];
        } else {
            const __half* A = (const __half*)Av;
            uint4 v0 = make_uint4(0,0,0,0), v1 = v0;
            if (m0 + arow < M) {
                const __half* ap = A + (size_t)(m0 + arow) * K + k0 + acolh;
                v0 = *(const uint4*)ap;
                v1 = *(const uint4*)(ap + 8);
            }
            *(uint4*)(As + arow * LDA + acolh)     = v0;
            *(uint4*)(As + arow * LDA + acolh + 8) = v1;
        }
        *(uint4*)(Bs + brow * LDB + bcolh) =
            *(const uint4*)(W + (size_t)(k0 + brow) * N + n0 + bcolh);
        __syncthreads();

#pragma unroll
        for (int kk = 0; kk < BK; kk += 16) {
            wmma::fragment<wmma::matrix_a, 16,16,16, __half, wmma::row_major> af[2];
            wmma::fragment<wmma::matrix_b, 16,16,16, __half, wmma::row_major> bf[2];
#pragma unroll
            for (int i = 0; i < 2; i++)
                wmma::load_matrix_sync(af[i], As + (wm * 32 + i * 16) * LDA + kk, LDA);
#pragma unroll
            for (int j = 0; j < 2; j++)
                wmma::load_matrix_sync(bf[j], Bs + kk * LDB + wn * 32 + j * 16, LDB);
#pragma unroll
            for (int i = 0; i < 2; i++)
#pragma unroll
                for (int j = 0; j < 2; j++)
                    wmma::mma_sync(acc[i][j], af[i], bf[j], acc[i][j]);
        }
        __syncthreads();
    }

#pragma unroll 1
    for (int mi = 0; mi < 2; mi++) {
        wmma::store_matrix_sync(&Es[warp][0],      acc[mi][0], LDE, wmma::mem_row_major);
        wmma::store_matrix_sync(&Es[warp][0] + 16, acc[mi][1], LDE, wmma::mem_row_major);
        __syncwarp();
        int r  = lane >> 1;
        int cb = (lane & 1) << 4;
        int m  = m0 + wm * 32 + mi * 16 + r;
        if (m < M) {
            int ncol = n0 + wn * 32 + cb;
            __half hv[16];
#pragma unroll
            for (int j = 0; j < 16; j++) {
                float x = Es[warp][r * LDE + cb + j] + bias[ncol + j];
                if (SILU) x = x / (1.0f + expf(-x));
                hv[j] = __float2half_rn(x);
            }
            uint4* dst = (uint4*)(C + (size_t)m * N + ncol);
            dst[0] = ((uint4*)hv)[0];
            dst[1] = ((uint4*)hv)[1];
        }
        __syncwarp();
    }
}

// ---------------------------------------------------------------------------
__device__ __forceinline__ void red_add4(float* p, float4 v) {
    asm volatile("red.global.add.v4.f32 [%0], {%1, %2, %3, %4};"
                 :: "l"(p), "f"(v.x), "f"(v.y), "f"(v.z), "f"(v.w)
                 : "memory");
}

// ---------------------------------------------------------------------------
// Edge kernel: round-11 config (256,2), dst-sorted + run-carry REDs — 230us.
// ---------------------------------------------------------------------------
__global__ __launch_bounds__(256, 2)
void edge_kernel(const int2*   __restrict__ sids,
                 const float4* __restrict__ sgeo,
                 const float*  __restrict__ Wf,
                 const float*  __restrict__ bf,
                 const __half* __restrict__ nvec,
                 const __half* __restrict__ so,
                 float* __restrict__ out_s,
                 float* __restrict__ out_v)
{
    __shared__ float s_Wf[NB * F3];
    __shared__ float s_basis[EPB * NB];
    __shared__ float s_cut[EPB];
    __shared__ int   s_src[EPB], s_dst[EPB];
    __shared__ float s_unit[3][EPB];
    __shared__ float s_d[EPB];
    __shared__ float s_bf[F3];

    const float PI_C = 0.628318530717958648f;

    int t  = threadIdx.x;
    int e0 = blockIdx.x * EPB;

    for (int i = t; i < NB * F3 / 4; i += 256)
        ((float4*)s_Wf)[i] = ((const float4*)Wf)[i];
    if (t < F3 / 4)
        ((float4*)s_bf)[t] = ((const float4*)bf)[t];

    if (t < EPB) {
        int e = e0 + t;
        int2 ei = sids[e];
        float4 g = sgeo[e];
        s_dst[t] = ei.x;
        s_src[t] = ei.y;
        float d = g.w;
        s_d[t] = d;
        s_cut[t] = (d < 5.0f) ? 0.5f * (cosf(d * PI_C) + 1.0f) : 0.0f;
        float inv = 1.0f / d;
        s_unit[0][t] = g.x * inv;
        s_unit[1][t] = g.y * inv;
        s_unit[2][t] = g.z * inv;
    }
    __syncthreads();

    for (int i = t; i < EPB * NB; i += 256) {
        int e = i / NB, n = i % NB;
        float d = s_d[e];
        float x = d * (float)(n + 1) * PI_C;
        x -= 6.2831853071795865f * rintf(x * 0.15915494309189534f);
        s_basis[i] = sinf(x) / d;
    }
    __syncthreads();

    int cg = t & 31;
    int eg = t >> 5;
    int cb = cg << 2;

#pragma unroll 1
    for (int pass = 0; pass < EPB / 32; pass++) {
        int egg = pass * 8 + eg;

        float acc[4][12];
#pragma unroll
        for (int i = 0; i < 4; i++)
#pragma unroll
            for (int j = 0; j < 12; j++) acc[i][j] = 0.0f;

        const float* bas = &s_basis[(egg << 2) * NB];
#pragma unroll
        for (int k = 0; k < NB; k++) {
            float be[4];
#pragma unroll
            for (int i = 0; i < 4; i++) be[i] = bas[i * NB + k];
            float4 w0 = *(float4*)&s_Wf[k * F3 + cb];
            float4 w1 = *(float4*)&s_Wf[k * F3 + FDIM + cb];
            float4 w2 = *(float4*)&s_Wf[k * F3 + 2 * FDIM + cb];
#pragma unroll
            for (int i = 0; i < 4; i++) {
                acc[i][0] += be[i] * w0.x; acc[i][1] += be[i] * w0.y;
                acc[i][2] += be[i] * w0.z; acc[i][3] += be[i] * w0.w;
                acc[i][4] += be[i] * w1.x; acc[i][5] += be[i] * w1.y;
                acc[i][6] += be[i] * w1.z; acc[i][7] += be[i] * w1.w;
                acc[i][8] += be[i] * w2.x; acc[i][9] += be[i] * w2.y;
                acc[i][10]+= be[i] * w2.z; acc[i][11]+= be[i] * w2.w;
            }
        }

        float4 c_s, c0, c1, c2;
        int cdst = -1;
#pragma unroll
        for (int i = 0; i < 4; i++) {
            int e   = (egg << 2) + i;
            int src = s_src[e];
            int dst = s_dst[e];
            float cw = s_cut[e];

            float4 bf0 = *(float4*)&s_bf[cb];
            float4 bf1 = *(float4*)&s_bf[FDIM + cb];
            float4 bf2 = *(float4*)&s_bf[2 * FDIM + cb];

            const __half* sor = so + (size_t)src * F3 + cb;
            float4 s0 = ld_half4(sor);
            float4 s1 = ld_half4(sor + FDIM);
            float4 s2 = ld_half4(sor + 2 * FDIM);

            float4 gs, ge, ms;
            gs.x = (acc[i][0] + bf0.x) * cw * s0.x;
            gs.y = (acc[i][1] + bf0.y) * cw * s0.y;
            gs.z = (acc[i][2] + bf0.z) * cw * s0.z;
            gs.w = (acc[i][3] + bf0.w) * cw * s0.w;
            ge.x = (acc[i][4] + bf1.x) * cw * s1.x;
            ge.y = (acc[i][5] + bf1.y) * cw * s1.y;
            ge.z = (acc[i][6] + bf1.z) * cw * s1.z;
            ge.w = (acc[i][7] + bf1.w) * cw * s1.w;
            ms.x = (acc[i][8] + bf2.x) * cw * s2.x;
            ms.y = (acc[i][9] + bf2.y) * cw * s2.y;
            ms.z = (acc[i][10]+ bf2.z) * cw * s2.z;
            ms.w = (acc[i][11]+ bf2.w) * cw * s2.w;

            const __half* nvp = nvec + (size_t)src * F3 + cb;
            float u0 = s_unit[0][e], u1 = s_unit[1][e], u2 = s_unit[2][e];

            float4 v, m0, m1, m2;
            v = ld_half4(nvp);
            m0.x = v.x * gs.x + ge.x * u0;  m0.y = v.y * gs.y + ge.y * u0;
            m0.z = v.z * gs.z + ge.z * u0;  m0.w = v.w * gs.w + ge.w * u0;
            v = ld_half4(nvp + FDIM);
            m1.x = v.x * gs.x + ge.x * u1;  m1.y = v.y * gs.y + ge.y * u1;
            m1.z = v.z * gs.z + ge.z * u1;  m1.w = v.w * gs.w + ge.w * u1;
            v = ld_half4(nvp + 2 * FDIM);
            m2.x = v.x * gs.x + ge.x * u2;  m2.y = v.y * gs.y + ge.y * u2;
            m2.z = v.z * gs.z + ge.z * u2;  m2.w = v.w * gs.w + ge.w * u2;

            if (i > 0 && dst == cdst) {
                c_s.x += ms.x; c_s.y += ms.y; c_s.z += ms.z; c_s.w += ms.w;
                c0.x += m0.x; c0.y += m0.y; c0.z += m0.z; c0.w += m0.w;
                c1.x += m1.x; c1.y += m1.y; c1.z += m1.z; c1.w += m1.w;
                c2.x += m2.x; c2.y += m2.y; c2.z += m2.z; c2.w += m2.w;
            } else {
                if (i > 0) {
                    red_add4(out_s + (size_t)cdst * FDIM + cb, c_s);
                    float* ov = out_v + (size_t)cdst * F3 + cb;
                    red_add4(ov, c0);
                    red_add4(ov + FDIM, c1);
                    red_add4(ov + 2 * FDIM, c2);
                }
                cdst = dst;
                c_s = ms; c0 = m0; c1 = m1; c2 = m2;
            }
        }
        red_add4(out_s + (size_t)cdst * FDIM + cb, c_s);
        float* ov = out_v + (size_t)cdst * F3 + cb;
        red_add4(ov, c0);
        red_add4(ov + FDIM, c1);
        red_add4(ov + 2 * FDIM, c2);
    }
}

// ---------------------------------------------------------------------------
extern "C" void kernel_launch(void* const* d_in, const int* in_sizes, int n_in,
                              void* d_out, int out_size) {
    const int2*  eidx  = (const int2*) d_in[0];
    const float* edist = (const float*)d_in[1];
    const float* ediff = (const float*)d_in[2];
    const float* ns    = (const float*)d_in[3];
    const float* nv    = (const float*)d_in[4];
    const float* Wf    = (const float*)d_in[5];
    const float* bf    = (const float*)d_in[6];
    const float* W1    = (const float*)d_in[7];
    const float* b1    = (const float*)d_in[8];
    const float* W2    = (const float*)d_in[9];
    const float* b2    = (const float*)d_in[10];
    float* out = (float*)d_out;

    __half *h_ptr, *so_ptr, *nvh_ptr, *w1h_ptr, *w2h_ptr;
    unsigned *cnt_ptr, *cur_ptr, *start_ptr, *bsum_ptr;
    int2 *sids_ptr; float4 *sgeo_ptr;
    cudaGetSymbolAddress((void**)&h_ptr,   g_h);
    cudaGetSymbolAddress((void**)&so_ptr,  g_so);
    cudaGetSymbolAddress((void**)&nvh_ptr, g_nvh);
    cudaGetSymbolAddress((void**)&w1h_ptr, g_W1h);
    cudaGetSymbolAddress((void**)&w2h_ptr, g_W2h);
    cudaGetSymbolAddress((void**)&cnt_ptr,   g_cnt);
    cudaGetSymbolAddress((void**)&cur_ptr,   g_cur);
    cudaGetSymbolAddress((void**)&start_ptr, g_start);
    cudaGetSymbolAddress((void**)&bsum_ptr,  g_bsum);
    cudaGetSymbolAddress((void**)&sids_ptr,  g_sids);
    cudaGetSymbolAddress((void**)&sgeo_ptr,  g_sgeo);

    // one-time side streams + events for fork/join inside graph capture
    static cudaStream_t s_sort = nullptr, s_copy = nullptr;
    static cudaEvent_t  s_fork = nullptr, s_join1 = nullptr, s_join2 = nullptr;
    if (s_sort == nullptr) {
        cudaStreamCreateWithFlags(&s_sort, cudaStreamNonBlocking);
        cudaStreamCreateWithFlags(&s_copy, cudaStreamNonBlocking);
        cudaEventCreateWithFlags(&s_fork,  cudaEventDisableTiming);
        cudaEventCreateWithFlags(&s_join1, cudaEventDisableTiming);
        cudaEventCreateWithFlags(&s_join2, cudaEventDisableTiming);
    }

    // ---- fork ------------------------------------------------------------
    cudaEventRecord(s_fork, 0);
    cudaStreamWaitEvent(s_sort, s_fork, 0);
    cudaStreamWaitEvent(s_copy, s_fork, 0);

    // side stream A: counting sort by dst
    zero_kernel<<<(NNODES + 255) / 256, 256, 0, s_sort>>>(cnt_ptr, cur_ptr);
    hist_kernel<<<(NEDGES + 255) / 256, 256, 0, s_sort>>>(eidx, cnt_ptr);
    blocksum_kernel<<<SCAN_NBLK, 256, 0, s_sort>>>(cnt_ptr, bsum_ptr);
    bsum_scan_kernel<<<1, 64, 0, s_sort>>>(bsum_ptr);
    block_scan_kernel<<<SCAN_NBLK, 256, 0, s_sort>>>(cnt_ptr, bsum_ptr, start_ptr);
    scatter_kernel<<<(NEDGES + 255) / 256, 256, 0, s_sort>>>(
        eidx, edist, ediff, start_ptr, cur_ptr, sids_ptr, sgeo_ptr);
    cudaEventRecord(s_join1, s_sort);

    // side stream B: out-init + nv fp16 copy
    int tot4 = (NNODES * FDIM + NNODES * F3) / 4;
    copy_init_kernel<<<(tot4 + 255) / 256, 256, 0, s_copy>>>(
        (const float4*)ns, (const float4*)nv, (float4*)out, (uint2*)nvh_ptr);
    cudaEventRecord(s_join2, s_copy);

    // main stream: MLP chain (hgemm1 reads fp32 ns directly)
    int wtot4 = (FDIM * FDIM + FDIM * F3) / 4;
    f2h_weights_kernel<<<(wtot4 + 255) / 256, 256>>>(
        (const float4*)W1, (const float4*)W2, (uint2*)w1h_ptr, (uint2*)w2h_ptr);

    hgemm_kernel<true, true><<<dim3((NNODES + 127) / 128, FDIM / 64), 256>>>(
        ns, w1h_ptr, b1, h_ptr, NNODES, FDIM);
    hgemm_kernel<false, false><<<dim3((NNODES + 127) / 128, F3 / 64), 256>>>(
        h_ptr, w2h_ptr, b2, so_ptr, NNODES, F3);

    // ---- join: edge kernel needs all three branches -----------------------
    cudaStreamWaitEvent(0, s_join1, 0);
    cudaStreamWaitEvent(0, s_join2, 0);
    edge_kernel<<<NEDGES / EPB, 256>>>(
        sids_ptr, sgeo_ptr, Wf, bf, nvh_ptr, so_ptr,
        out, out + (size_t)NNODES * FDIM);
}

// round 15
// speedup vs baseline: 1.0236x; 1.0236x over previous
#include <cuda_runtime.h>
#include <cuda_fp16.h>
#include <mma.h>
#include <math.h>

using namespace nvcuda;

#define NNODES 50000
#define NEDGES 400000
#define FDIM   128
#define F3     384
#define NB     20
#define EPB    128
#define SCAN_NBLK 49   // ceil(50000/1024)
#define GBUF_BYTES (8 * 4 * 2 * F3 * 2)   // 49152: 8 warps x 4 edges x {so,nv} x 384 half

__device__ __half g_h [(size_t)NNODES * FDIM];
__device__ __half g_so[(size_t)NNODES * F3];
__device__ __half g_nvh[(size_t)NNODES * F3];
__device__ __half g_W1h[FDIM * FDIM];
__device__ __half g_W2h[FDIM * F3];

// counting-sort scratch
__device__ unsigned g_cnt[NNODES];
__device__ unsigned g_cur[NNODES];
__device__ unsigned g_start[NNODES];
__device__ unsigned g_bsum[64];
__device__ int2     g_sids[NEDGES];     // (dst, src) sorted by dst
__device__ float4   g_sgeo[NEDGES];     // (diffx, diffy, diffz, dist)

// ---------------------------------------------------------------------------
__global__ void copy_init_kernel(const float4* __restrict__ ns,
                                 const float4* __restrict__ nv,
                                 float4* __restrict__ out,
                                 uint2* __restrict__ nvh) {
    const int NS4 = NNODES * FDIM / 4;
    const int NT4 = NS4 + NNODES * F3 / 4;
    int i = blockIdx.x * blockDim.x + threadIdx.x;
    if (i >= NT4) return;
    if (i < NS4) {
        out[i] = ns[i];
    } else {
        float4 v = nv[i - NS4];
        out[i] = v;
        __half2 h0 = __floats2half2_rn(v.x, v.y);
        __half2 h1 = __floats2half2_rn(v.z, v.w);
        nvh[i - NS4] = make_uint2(*(unsigned*)&h0, *(unsigned*)&h1);
    }
}

__global__ void f2h_weights_kernel(const float4* __restrict__ w1,
                                   const float4* __restrict__ w2,
                                   uint2* __restrict__ w1h,
                                   uint2* __restrict__ w2h) {
    const int N1 = FDIM * FDIM / 4;
    const int NT = N1 + FDIM * F3 / 4;
    int i = blockIdx.x * blockDim.x + threadIdx.x;
    if (i >= NT) return;
    float4 v;
    if (i < N1) v = w1[i]; else v = w2[i - N1];
    __half2 h0 = __floats2half2_rn(v.x, v.y);
    __half2 h1 = __floats2half2_rn(v.z, v.w);
    uint2 o = make_uint2(*(unsigned*)&h0, *(unsigned*)&h1);
    if (i < N1) w1h[i] = o; else w2h[i - N1] = o;
}

__device__ __forceinline__ float4 ld_half4(const __half* p) {
    uint2 u = *(const uint2*)p;
    __half2 h0 = *reinterpret_cast<__half2*>(&u.x);
    __half2 h1 = *reinterpret_cast<__half2*>(&u.y);
    float2 f0 = __half22float2(h0), f1 = __half22float2(h1);
    return make_float4(f0.x, f0.y, f1.x, f1.y);
}

// ---------------------------------------------------------------------------
// counting sort by dst — hierarchical scan
// ---------------------------------------------------------------------------
__global__ void zero_kernel(unsigned* a, unsigned* b) {
    int i = blockIdx.x * blockDim.x + threadIdx.x;
    if (i < NNODES) { a[i] = 0u; b[i] = 0u; }
}

__global__ void hist_kernel(const int2* __restrict__ eidx, unsigned* cnt) {
    int e = blockIdx.x * blockDim.x + threadIdx.x;
    if (e < NEDGES) atomicAdd(&cnt[eidx[e].x], 1u);
}

__global__ void blocksum_kernel(const unsigned* __restrict__ cnt,
                                unsigned* __restrict__ bsum) {
    __shared__ unsigned sh[256];
    int base = blockIdx.x * 1024;
    unsigned s = 0;
#pragma unroll
    for (int j = 0; j < 4; j++) {
        int idx = base + threadIdx.x + j * 256;
        if (idx < NNODES) s += cnt[idx];
    }
    sh[threadIdx.x] = s;
    __syncthreads();
    for (int off = 128; off > 0; off >>= 1) {
        if (threadIdx.x < off) sh[threadIdx.x] += sh[threadIdx.x + off];
        __syncthreads();
    }
    if (threadIdx.x == 0) bsum[blockIdx.x] = sh[0];
}

__global__ void bsum_scan_kernel(unsigned* bsum) {
    __shared__ unsigned sh[64];
    unsigned v = (threadIdx.x < SCAN_NBLK) ? bsum[threadIdx.x] : 0u;
    sh[threadIdx.x] = v;
    __syncthreads();
    for (int off = 1; off < 64; off <<= 1) {
        unsigned t = (threadIdx.x >= (unsigned)off) ? sh[threadIdx.x - off] : 0u;
        __syncthreads();
        sh[threadIdx.x] += t;
        __syncthreads();
    }
    if (threadIdx.x < SCAN_NBLK) bsum[threadIdx.x] = sh[threadIdx.x] - v;
}

__global__ void block_scan_kernel(const unsigned* __restrict__ cnt,
                                  const unsigned* __restrict__ bsum,
                                  unsigned* __restrict__ start) {
    __shared__ unsigned sh[256];
    int base = blockIdx.x * 1024;
    unsigned v[4];
    unsigned s = 0;
#pragma unroll
    for (int j = 0; j < 4; j++) {
        int idx = base + (int)threadIdx.x * 4 + j;
        v[j] = (idx < NNODES) ? cnt[idx] : 0u;
        s += v[j];
    }
    sh[threadIdx.x] = s;
    __syncthreads();
    for (int off = 1; off < 256; off <<= 1) {
        unsigned t = (threadIdx.x >= (unsigned)off) ? sh[threadIdx.x - off] : 0u;
        __syncthreads();
        sh[threadIdx.x] += t;
        __syncthreads();
    }
    unsigned ex = bsum[blockIdx.x] + sh[threadIdx.x] - s;
#pragma unroll
    for (int j = 0; j < 4; j++) {
        int idx = base + (int)threadIdx.x * 4 + j;
        if (idx < NNODES) start[idx] = ex;
        ex += v[j];
    }
}

__global__ void scatter_kernel(const int2*  __restrict__ eidx,
                               const float* __restrict__ edist,
                               const float* __restrict__ ediff,
                               const unsigned* __restrict__ start,
                               unsigned* __restrict__ cur,
                               int2* __restrict__ sids,
                               float4* __restrict__ sgeo) {
    int e = blockIdx.x * blockDim.x + threadIdx.x;
    if (e >= NEDGES) return;
    int2 ei = eidx[e];
    unsigned pos = start[ei.x] + atomicAdd(&cur[ei.x], 1u);
    sids[pos] = ei;
    sgeo[pos] = make_float4(ediff[3*e], ediff[3*e+1], ediff[3*e+2], edist[e]);
}

// ---------------------------------------------------------------------------
// Tensor-core node MLP GEMM. AF32: A operand read as fp32, converted inline.
// ---------------------------------------------------------------------------
template<bool SILU, bool AF32>
__global__ __launch_bounds__(256)
void hgemm_kernel(const void* __restrict__ Av, const __half* __restrict__ W,
                  const float* __restrict__ bias, __half* __restrict__ C,
                  int M, int N)
{
    const int K = 128, BM = 128, BK = 32;
    const int LDA = 48, LDB = 72, LDE = 36;
    __shared__ __half As[BM * LDA];
    __shared__ __half Bs[BK * LDB];
    __shared__ float  Es[8][16 * LDE];

    int t = threadIdx.x;
    int warp = t >> 5, lane = t & 31;
    int wm = warp >> 1, wn = warp & 1;
    int m0 = blockIdx.x * BM;
    int n0 = blockIdx.y * 64;

    wmma::fragment<wmma::accumulator, 16, 16, 16, float> acc[2][2];
#pragma unroll
    for (int i = 0; i < 2; i++)
#pragma unroll
        for (int j = 0; j < 2; j++) wmma::fill_fragment(acc[i][j], 0.0f);

    int arow = t >> 1, acolh = (t & 1) << 4;
    int brow = t >> 3, bcolh = (t & 7) << 3;

#pragma unroll 1
    for (int k0 = 0; k0 < K; k0 += BK) {
        if (AF32) {
            const float* A = (const float*)Av;
            __half hv[16];
#pragma unroll
            for (int q = 0; q < 16; q++) hv[q] = __float2half_rn(0.f);
            if (m0 + arow < M) {
                const float* ap = A + (size_t)(m0 + arow) * K + k0 + acolh;
#pragma unroll
                for (int q = 0; q < 4; q++) {
                    float4 f = *(const float4*)(ap + q * 4);
                    hv[q*4+0] = __float2half_rn(f.x);
                    hv[q*4+1] = __float2half_rn(f.y);
                    hv[q*4+2] = __float2half_rn(f.z);
                    hv[q*4+3] = __float2half_rn(f.w);
                }
            }
            *(uint4*)(As + arow * LDA + acolh)     = ((uint4*)hv)[0];
            *(uint4*)(As + arow * LDA + acolh + 8) = ((uint4*)hv)[1];
        } else {
            const __half* A = (const __half*)Av;
            uint4 v0 = make_uint4(0,0,0,0), v1 = v0;
            if (m0 + arow < M) {
                const __half* ap = A + (size_t)(m0 + arow) * K + k0 + acolh;
                v0 = *(const uint4*)ap;
                v1 = *(const uint4*)(ap + 8);
            }
            *(uint4*)(As + arow * LDA + acolh)     = v0;
            *(uint4*)(As + arow * LDA + acolh + 8) = v1;
        }
        *(uint4*)(Bs + brow * LDB + bcolh) =
            *(const uint4*)(W + (size_t)(k0 + brow) * N + n0 + bcolh);
        __syncthreads();

#pragma unroll
        for (int kk = 0; kk < BK; kk += 16) {
            wmma::fragment<wmma::matrix_a, 16,16,16, __half, wmma::row_major> af[2];
            wmma::fragment<wmma::matrix_b, 16,16,16, __half, wmma::row_major> bf[2];
#pragma unroll
            for (int i = 0; i < 2; i++)
                wmma::load_matrix_sync(af[i], As + (wm * 32 + i * 16) * LDA + kk, LDA);
#pragma unroll
            for (int j = 0; j < 2; j++)
                wmma::load_matrix_sync(bf[j], Bs + kk * LDB + wn * 32 + j * 16, LDB);
#pragma unroll
            for (int i = 0; i < 2; i++)
#pragma unroll
                for (int j = 0; j < 2; j++)
                    wmma::mma_sync(acc[i][j], af[i], bf[j], acc[i][j]);
        }
        __syncthreads();
    }

#pragma unroll 1
    for (int mi = 0; mi < 2; mi++) {
        wmma::store_matrix_sync(&Es[warp][0],      acc[mi][0], LDE, wmma::mem_row_major);
        wmma::store_matrix_sync(&Es[warp][0] + 16, acc[mi][1], LDE, wmma::mem_row_major);
        __syncwarp();
        int r  = lane >> 1;
        int cb = (lane & 1) << 4;
        int m  = m0 + wm * 32 + mi * 16 + r;
        if (m < M) {
            int ncol = n0 + wn * 32 + cb;
            __half hv[16];
#pragma unroll
            for (int j = 0; j < 16; j++) {
                float x = Es[warp][r * LDE + cb + j] + bias[ncol + j];
                if (SILU) x = x / (1.0f + expf(-x));
                hv[j] = __float2half_rn(x);
            }
            uint4* dst = (uint4*)(C + (size_t)m * N + ncol);
            dst[0] = ((uint4*)hv)[0];
            dst[1] = ((uint4*)hv)[1];
        }
        __syncwarp();
    }
}

// ---------------------------------------------------------------------------
__device__ __forceinline__ void red_add4(float* p, float4 v) {
    asm volatile("red.global.add.v4.f32 [%0], {%1, %2, %3, %4};"
                 :: "l"(p), "f"(v.x), "f"(v.y), "f"(v.z), "f"(v.w)
                 : "memory");
}

// ---------------------------------------------------------------------------
// Edge kernel: dst-sorted + run-carry REDs + NEW: per-warp cp.async prefetch
// of so/nvec gather rows into smem, hidden under the filter GEMM.
// ---------------------------------------------------------------------------
__global__ __launch_bounds__(256, 2)
void edge_kernel(const int2*   __restrict__ sids,
                 const float4* __restrict__ sgeo,
                 const float*  __restrict__ Wf,
                 const float*  __restrict__ bf,
                 const __half* __restrict__ nvec,
                 const __half* __restrict__ so,
                 float* __restrict__ out_s,
                 float* __restrict__ out_v)
{
    __shared__ float s_Wf[NB * F3];
    __shared__ float s_basis[EPB * NB];
    __shared__ float s_cut[EPB];
    __shared__ int   s_src[EPB], s_dst[EPB];
    __shared__ float s_unit[3][EPB];
    __shared__ float s_d[EPB];
    __shared__ float s_bf[F3];
    extern __shared__ __half s_gbuf[];   // [8 warps][4 edges][2 arrays][384]

    const float PI_C = 0.628318530717958648f;

    int t  = threadIdx.x;
    int e0 = blockIdx.x * EPB;

    for (int i = t; i < NB * F3 / 4; i += 256)
        ((float4*)s_Wf)[i] = ((const float4*)Wf)[i];
    if (t < F3 / 4)
        ((float4*)s_bf)[t] = ((const float4*)bf)[t];

    if (t < EPB) {
        int e = e0 + t;
        int2 ei = sids[e];
        float4 g = sgeo[e];
        s_dst[t] = ei.x;
        s_src[t] = ei.y;
        float d = g.w;
        s_d[t] = d;
        s_cut[t] = (d < 5.0f) ? 0.5f * (cosf(d * PI_C) + 1.0f) : 0.0f;
        float inv = 1.0f / d;
        s_unit[0][t] = g.x * inv;
        s_unit[1][t] = g.y * inv;
        s_unit[2][t] = g.z * inv;
    }
    __syncthreads();

    for (int i = t; i < EPB * NB; i += 256) {
        int e = i / NB, n = i % NB;
        float d = s_d[e];
        float x = d * (float)(n + 1) * PI_C;
        x -= 6.2831853071795865f * rintf(x * 0.15915494309189534f);
        s_basis[i] = sinf(x) / d;
    }
    __syncthreads();

    int cg = t & 31;
    int eg = t >> 5;
    int cb = cg << 2;

#pragma unroll 1
    for (int pass = 0; pass < EPB / 32; pass++) {
        int egg = pass * 8 + eg;

        // ---- prefetch this pass's gather rows (warp-private buffer) ----
        {
#pragma unroll
            for (int j = 0; j < 12; j++) {
                int c   = cg + (j << 5);          // 0..383 chunk id within warp
                int ei  = c / 96;                 // edge 0..3
                int r   = c - ei * 96;            // 0..95
                int arr = r / 48;                 // 0=so, 1=nv
                int off = (r - arr * 48) << 3;    // half offset (16B chunks)
                int e   = (egg << 2) + ei;
                const __half* gp = (arr == 0 ? so : nvec)
                                   + (size_t)s_src[e] * F3 + off;
                __half* sp = s_gbuf + (((eg << 2) + ei) * 2 + arr) * F3 + off;
                unsigned sa = (unsigned)__cvta_generic_to_shared(sp);
                asm volatile("cp.async.cg.shared.global [%0], [%1], 16;"
                             :: "r"(sa), "l"(gp) : "memory");
            }
            asm volatile("cp.async.commit_group;" ::: "memory");
        }

        // ---- filter GEMM (hides the prefetch latency) ----
        float acc[4][12];
#pragma unroll
        for (int i = 0; i < 4; i++)
#pragma unroll
            for (int j = 0; j < 12; j++) acc[i][j] = 0.0f;

        const float* bas = &s_basis[(egg << 2) * NB];
#pragma unroll
        for (int k = 0; k < NB; k++) {
            float be[4];
#pragma unroll
            for (int i = 0; i < 4; i++) be[i] = bas[i * NB + k];
            float4 w0 = *(float4*)&s_Wf[k * F3 + cb];
            float4 w1 = *(float4*)&s_Wf[k * F3 + FDIM + cb];
            float4 w2 = *(float4*)&s_Wf[k * F3 + 2 * FDIM + cb];
#pragma unroll
            for (int i = 0; i < 4; i++) {
                acc[i][0] += be[i] * w0.x; acc[i][1] += be[i] * w0.y;
                acc[i][2] += be[i] * w0.z; acc[i][3] += be[i] * w0.w;
                acc[i][4] += be[i] * w1.x; acc[i][5] += be[i] * w1.y;
                acc[i][6] += be[i] * w1.z; acc[i][7] += be[i] * w1.w;
                acc[i][8] += be[i] * w2.x; acc[i][9] += be[i] * w2.y;
                acc[i][10]+= be[i] * w2.z; acc[i][11]+= be[i] * w2.w;
            }
        }

        asm volatile("cp.async.wait_group 0;" ::: "memory");
        __syncwarp();

        // ---- epilogue: gathers now in smem ----
        float4 c_s, c0, c1, c2;
        int cdst = -1;
#pragma unroll
        for (int i = 0; i < 4; i++) {
            int e   = (egg << 2) + i;
            int dst = s_dst[e];
            float cw = s_cut[e];

            float4 bf0 = *(float4*)&s_bf[cb];
            float4 bf1 = *(float4*)&s_bf[FDIM + cb];
            float4 bf2 = *(float4*)&s_bf[2 * FDIM + cb];

            const __half* sor = s_gbuf + (((eg << 2) + i) * 2 + 0) * F3 + cb;
            const __half* nvp = s_gbuf + (((eg << 2) + i) * 2 + 1) * F3 + cb;

            float4 s0 = ld_half4(sor);
            float4 s1 = ld_half4(sor + FDIM);
            float4 s2 = ld_half4(sor + 2 * FDIM);

            float4 gs, ge, ms;
            gs.x = (acc[i][0] + bf0.x) * cw * s0.x;
            gs.y = (acc[i][1] + bf0.y) * cw * s0.y;
            gs.z = (acc[i][2] + bf0.z) * cw * s0.z;
            gs.w = (acc[i][3] + bf0.w) * cw * s0.w;
            ge.x = (acc[i][4] + bf1.x) * cw * s1.x;
            ge.y = (acc[i][5] + bf1.y) * cw * s1.y;
            ge.z = (acc[i][6] + bf1.z) * cw * s1.z;
            ge.w = (acc[i][7] + bf1.w) * cw * s1.w;
            ms.x = (acc[i][8] + bf2.x) * cw * s2.x;
            ms.y = (acc[i][9] + bf2.y) * cw * s2.y;
            ms.z = (acc[i][10]+ bf2.z) * cw * s2.z;
            ms.w = (acc[i][11]+ bf2.w) * cw * s2.w;

            float u0 = s_unit[0][e], u1 = s_unit[1][e], u2 = s_unit[2][e];

            float4 v, m0, m1, m2;
            v = ld_half4(nvp);
            m0.x = v.x * gs.x + ge.x * u0;  m0.y = v.y * gs.y + ge.y * u0;
            m0.z = v.z * gs.z + ge.z * u0;  m0.w = v.w * gs.w + ge.w * u0;
            v = ld_half4(nvp + FDIM);
            m1.x = v.x * gs.x + ge.x * u1;  m1.y = v.y * gs.y + ge.y * u1;
            m1.z = v.z * gs.z + ge.z * u1;  m1.w = v.w * gs.w + ge.w * u1;
            v = ld_half4(nvp + 2 * FDIM);
            m2.x = v.x * gs.x + ge.x * u2;  m2.y = v.y * gs.y + ge.y * u2;
            m2.z = v.z * gs.z + ge.z * u2;  m2.w = v.w * gs.w + ge.w * u2;

            if (i > 0 && dst == cdst) {
                c_s.x += ms.x; c_s.y += ms.y; c_s.z += ms.z; c_s.w += ms.w;
                c0.x += m0.x; c0.y += m0.y; c0.z += m0.z; c0.w += m0.w;
                c1.x += m1.x; c1.y += m1.y; c1.z += m1.z; c1.w += m1.w;
                c2.x += m2.x; c2.y += m2.y; c2.z += m2.z; c2.w += m2.w;
            } else {
                if (i > 0) {
                    red_add4(out_s + (size_t)cdst * FDIM + cb, c_s);
                    float* ov = out_v + (size_t)cdst * F3 + cb;
                    red_add4(ov, c0);
                    red_add4(ov + FDIM, c1);
                    red_add4(ov + 2 * FDIM, c2);
                }
                cdst = dst;
                c_s = ms; c0 = m0; c1 = m1; c2 = m2;
            }
        }
        red_add4(out_s + (size_t)cdst * FDIM + cb, c_s);
        float* ov = out_v + (size_t)cdst * F3 + cb;
        red_add4(ov, c0);
        red_add4(ov + FDIM, c1);
        red_add4(ov + 2 * FDIM, c2);
    }
}

// ---------------------------------------------------------------------------
extern "C" void kernel_launch(void* const* d_in, const int* in_sizes, int n_in,
                              void* d_out, int out_size) {
    const int2*  eidx  = (const int2*) d_in[0];
    const float* edist = (const float*)d_in[1];
    const float* ediff = (const float*)d_in[2];
    const float* ns    = (const float*)d_in[3];
    const float* nv    = (const float*)d_in[4];
    const float* Wf    = (const float*)d_in[5];
    const float* bf    = (const float*)d_in[6];
    const float* W1    = (const float*)d_in[7];
    const float* b1    = (const float*)d_in[8];
    const float* W2    = (const float*)d_in[9];
    const float* b2    = (const float*)d_in[10];
    float* out = (float*)d_out;

    __half *h_ptr, *so_ptr, *nvh_ptr, *w1h_ptr, *w2h_ptr;
    unsigned *cnt_ptr, *cur_ptr, *start_ptr, *bsum_ptr;
    int2 *sids_ptr; float4 *sgeo_ptr;
    cudaGetSymbolAddress((void**)&h_ptr,   g_h);
    cudaGetSymbolAddress((void**)&so_ptr,  g_so);
    cudaGetSymbolAddress((void**)&nvh_ptr, g_nvh);
    cudaGetSymbolAddress((void**)&w1h_ptr, g_W1h);
    cudaGetSymbolAddress((void**)&w2h_ptr, g_W2h);
    cudaGetSymbolAddress((void**)&cnt_ptr,   g_cnt);
    cudaGetSymbolAddress((void**)&cur_ptr,   g_cur);
    cudaGetSymbolAddress((void**)&start_ptr, g_start);
    cudaGetSymbolAddress((void**)&bsum_ptr,  g_bsum);
    cudaGetSymbolAddress((void**)&sids_ptr,  g_sids);
    cudaGetSymbolAddress((void**)&sgeo_ptr,  g_sgeo);

    // one-time side streams + events + smem opt-in
    static cudaStream_t s_sort = nullptr, s_copy = nullptr;
    static cudaEvent_t  s_fork = nullptr, s_join1 = nullptr, s_join2 = nullptr;
    if (s_sort == nullptr) {
        cudaStreamCreateWithFlags(&s_sort, cudaStreamNonBlocking);
        cudaStreamCreateWithFlags(&s_copy, cudaStreamNonBlocking);
        cudaEventCreateWithFlags(&s_fork,  cudaEventDisableTiming);
        cudaEventCreateWithFlags(&s_join1, cudaEventDisableTiming);
        cudaEventCreateWithFlags(&s_join2, cudaEventDisableTiming);
        cudaFuncSetAttribute(edge_kernel,
                             cudaFuncAttributeMaxDynamicSharedMemorySize,
                             GBUF_BYTES);
    }

    // ---- fork ------------------------------------------------------------
    cudaEventRecord(s_fork, 0);
    cudaStreamWaitEvent(s_sort, s_fork, 0);
    cudaStreamWaitEvent(s_copy, s_fork, 0);

    // side stream A: counting sort by dst
    zero_kernel<<<(NNODES + 255) / 256, 256, 0, s_sort>>>(cnt_ptr, cur_ptr);
    hist_kernel<<<(NEDGES + 255) / 256, 256, 0, s_sort>>>(eidx, cnt_ptr);
    blocksum_kernel<<<SCAN_NBLK, 256, 0, s_sort>>>(cnt_ptr, bsum_ptr);
    bsum_scan_kernel<<<1, 64, 0, s_sort>>>(bsum_ptr);
    block_scan_kernel<<<SCAN_NBLK, 256, 0, s_sort>>>(cnt_ptr, bsum_ptr, start_ptr);
    scatter_kernel<<<(NEDGES + 255) / 256, 256, 0, s_sort>>>(
        eidx, edist, ediff, start_ptr, cur_ptr, sids_ptr, sgeo_ptr);
    cudaEventRecord(s_join1, s_sort);

    // side stream B: out-init + nv fp16 copy
    int tot4 = (NNODES * FDIM + NNODES * F3) / 4;
    copy_init_kernel<<<(tot4 + 255) / 256, 256, 0, s_copy>>>(
        (const float4*)ns, (const float4*)nv, (float4*)out, (uint2*)nvh_ptr);
    cudaEventRecord(s_join2, s_copy);

    // main stream: MLP chain (hgemm1 reads fp32 ns directly)
    int wtot4 = (FDIM * FDIM + FDIM * F3) / 4;
    f2h_weights_kernel<<<(wtot4 + 255) / 256, 256>>>(
        (const float4*)W1, (const float4*)W2, (uint2*)w1h_ptr, (uint2*)w2h_ptr);

    hgemm_kernel<true, true><<<dim3((NNODES + 127) / 128, FDIM / 64), 256>>>(
        ns, w1h_ptr, b1, h_ptr, NNODES, FDIM);
    hgemm_kernel<false, false><<<dim3((NNODES + 127) / 128, F3 / 64), 256>>>(
        h_ptr, w2h_ptr, b2, so_ptr, NNODES, F3);

    // ---- join: edge kernel needs all three branches -----------------------
    cudaStreamWaitEvent(0, s_join1, 0);
    cudaStreamWaitEvent(0, s_join2, 0);
    edge_kernel<<<NEDGES / EPB, 256, GBUF_BYTES>>>(
        sids_ptr, sgeo_ptr, Wf, bf, nvh_ptr, so_ptr,
        out, out + (size_t)NNODES * FDIM);
}